// round 1
// baseline (speedup 1.0000x reference)
#include <cuda_runtime.h>
#include <cuda_fp16.h>
#include <cstdint>
#include <cstddef>

#define LSEQ 512
#define NBATCH 512
#define IDIM 128
#define HDIM 128
#define GDIM 512   // 4*H

// Scratch: pre-activation input gates Xg[L*N, 4H] fp32 (512 MB, static device bss)
__device__ float g_Xg[(size_t)LSEQ * NBATCH * GDIM];

// ---------------------------------------------------------------------------
// helpers
// ---------------------------------------------------------------------------
__device__ __forceinline__ uint32_t f2h2(float a, float b) {
    __half2 h = __floats2half2_rn(a, b);
    return *reinterpret_cast<uint32_t*>(&h);
}

__device__ __forceinline__ void mma16816(float* d,
    uint32_t a0, uint32_t a1, uint32_t a2, uint32_t a3,
    uint32_t b0, uint32_t b1)
{
    asm volatile(
        "mma.sync.aligned.m16n8k16.row.col.f32.f16.f16.f32 "
        "{%0,%1,%2,%3}, {%4,%5,%6,%7}, {%8,%9}, {%0,%1,%2,%3};\n"
        : "+f"(d[0]), "+f"(d[1]), "+f"(d[2]), "+f"(d[3])
        : "r"(a0), "r"(a1), "r"(a2), "r"(a3), "r"(b0), "r"(b1));
}

__device__ __forceinline__ float ex2f(float x) {
    float y; asm("ex2.approx.f32 %0, %1;" : "=f"(y) : "f"(x)); return y;
}
__device__ __forceinline__ float rcpf(float x) {
    float y; asm("rcp.approx.f32 %0, %1;" : "=f"(y) : "f"(x)); return y;
}
// accurate sigmoid/tanh (EX2 ~2ulp, RCP ~1ulp) — NOT tanh.approx (5e-4 abs err)
__device__ __forceinline__ float sigf(float x) {
    return rcpf(1.0f + ex2f(-1.44269504f * x));
}
__device__ __forceinline__ float tanh_fast(float x) {
    return __fmaf_rn(2.0f, sigf(2.0f * x), -1.0f);
}

// ---------------------------------------------------------------------------
// Phase 1: Xg[m, g] = sum_k x[m,k] * W_ih[g,k] + (b_ih[g] + b_hh[g])
// M = L*N = 262144, G = 512, K = 128. Block: 32 M-rows, 512 threads (16 warps).
// Warp w owns gate columns [32w, 32w+32): 4 n8 tiles. B frags (W_ih) in regs.
// ---------------------------------------------------------------------------
__global__ void __launch_bounds__(512, 1)
pregemm_kernel(const float* __restrict__ x,
               const float* __restrict__ Wih,
               const float* __restrict__ bih,
               const float* __restrict__ bhh)
{
    __shared__ __half Ash[32][136];   // padded: 272B row pitch, conflict-free frags

    const int tid  = threadIdx.x;
    const int warp = tid >> 5;
    const int lane = tid & 31;
    const int m0   = blockIdx.x * 32;
    const int colBase = warp * 32;

    // --- load + convert A tile (32 x 128 fp32 -> fp16 smem) ---
    {
        const int r = tid >> 4;            // 0..31
        const int c = (tid & 15) * 8;      // 0..120
        const float4* p = reinterpret_cast<const float4*>(x + (size_t)(m0 + r) * IDIM + c);
        float4 v0 = p[0];
        float4 v1 = p[1];
        __half2* s = reinterpret_cast<__half2*>(&Ash[r][c]);
        s[0] = __floats2half2_rn(v0.x, v0.y);
        s[1] = __floats2half2_rn(v0.z, v0.w);
        s[2] = __floats2half2_rn(v1.x, v1.y);
        s[3] = __floats2half2_rn(v1.z, v1.w);
    }

    // --- B fragments: W_ih rows for this warp's 32 gate columns ---
    uint32_t bfrag[4][8][2];
#pragma unroll
    for (int j = 0; j < 4; j++) {
        const int n = colBase + j * 8 + (lane >> 2);
        const float* wr = Wih + (size_t)n * IDIM;
#pragma unroll
        for (int kt = 0; kt < 8; kt++) {
            const int k = kt * 16 + (lane & 3) * 2;
            float2 w0 = *reinterpret_cast<const float2*>(wr + k);
            float2 w1 = *reinterpret_cast<const float2*>(wr + k + 8);
            bfrag[j][kt][0] = f2h2(w0.x, w0.y);
            bfrag[j][kt][1] = f2h2(w1.x, w1.y);
        }
    }

    // --- bias pairs for this lane's output columns ---
    float2 bsum[4];
#pragma unroll
    for (int j = 0; j < 4; j++) {
        const int col = colBase + j * 8 + (lane & 3) * 2;
        bsum[j].x = bih[col]     + bhh[col];
        bsum[j].y = bih[col + 1] + bhh[col + 1];
    }

    __syncthreads();

    float acc[2][4][4];
#pragma unroll
    for (int mi = 0; mi < 2; mi++)
#pragma unroll
        for (int j = 0; j < 4; j++)
#pragma unroll
            for (int q = 0; q < 4; q++) acc[mi][j][q] = 0.0f;

#pragma unroll
    for (int kt = 0; kt < 8; kt++) {
        const int k = kt * 16 + (lane & 3) * 2;
#pragma unroll
        for (int mi = 0; mi < 2; mi++) {
            const int r = mi * 16 + (lane >> 2);
            uint32_t a0 = *reinterpret_cast<const uint32_t*>(&Ash[r][k]);
            uint32_t a1 = *reinterpret_cast<const uint32_t*>(&Ash[r + 8][k]);
            uint32_t a2 = *reinterpret_cast<const uint32_t*>(&Ash[r][k + 8]);
            uint32_t a3 = *reinterpret_cast<const uint32_t*>(&Ash[r + 8][k + 8]);
#pragma unroll
            for (int j = 0; j < 4; j++)
                mma16816(acc[mi][j], a0, a1, a2, a3, bfrag[j][kt][0], bfrag[j][kt][1]);
        }
    }

    // --- epilogue: add bias, store Xg ---
#pragma unroll
    for (int mi = 0; mi < 2; mi++) {
#pragma unroll
        for (int j = 0; j < 4; j++) {
            const int row = m0 + mi * 16 + (lane >> 2);
            const int col = colBase + j * 8 + (lane & 3) * 2;
            float2 v0 = make_float2(acc[mi][j][0] + bsum[j].x, acc[mi][j][1] + bsum[j].y);
            float2 v1 = make_float2(acc[mi][j][2] + bsum[j].x, acc[mi][j][3] + bsum[j].y);
            *reinterpret_cast<float2*>(&g_Xg[(size_t)row * GDIM + col])       = v0;
            *reinterpret_cast<float2*>(&g_Xg[(size_t)(row + 8) * GDIM + col]) = v1;
        }
    }
}

// ---------------------------------------------------------------------------
// Phase 2: masked LSTM recurrence.
// Grid: 32 blocks x 16 batch rows. 512 threads (16 warps).
// W_hh lives entirely in per-warp B-fragments (64 regs/thread) — loaded once.
// h: fp16 in smem (padded). c: fp32 in registers of the owning epilogue thread.
// Per step: MMA -> gate exchange via smem -> activations -> state update.
// ---------------------------------------------------------------------------
__global__ void __launch_bounds__(512, 1)
lstm_rec_kernel(const float* __restrict__ hc,
                const int*   __restrict__ is_init,
                const float* __restrict__ Whh,
                float* __restrict__ out)
{
    __shared__ __half hsh[16][136];    // h state, padded (272B pitch, conflict-free)
    __shared__ float  gsh[16][520];    // gate preacts exchange buffer

    const int tid  = threadIdx.x;
    const int warp = tid >> 5;
    const int lane = tid & 31;
    const int n0   = blockIdx.x * 16;
    const int colBase = warp * 32;

    const int hcol = tid & 127;        // epilogue ownership: (row, hcol)
    const int rb   = tid >> 7;         // 0..3 ; rows rb, rb+4, rb+8, rb+12

    // --- W_hh B-fragments, loaded once (fp32 -> fp16) ---
    uint32_t bfrag[4][8][2];
#pragma unroll
    for (int j = 0; j < 4; j++) {
        const int n = colBase + j * 8 + (lane >> 2);
        const float* wr = Whh + (size_t)n * HDIM;
#pragma unroll
        for (int kt = 0; kt < 8; kt++) {
            const int k = kt * 16 + (lane & 3) * 2;
            float2 w0 = *reinterpret_cast<const float2*>(wr + k);
            float2 w1 = *reinterpret_cast<const float2*>(wr + k + 8);
            bfrag[j][kt][0] = f2h2(w0.x, w0.y);
            bfrag[j][kt][1] = f2h2(w1.x, w1.y);
        }
    }

    // --- init state: h0*m0 -> smem fp16 ; c0*m0 -> regs ---
    float creg[4];
#pragma unroll
    for (int j = 0; j < 4; j++) {
        const int row = rb + 4 * j;
        const int n = n0 + row;
        const float m0 = 1.0f - (float)is_init[n];             // t = 0 mask
        const float h0 = hc[(size_t)n * 256 + hcol] * m0;
        creg[j]        = hc[(size_t)n * 256 + 128 + hcol] * m0;
        hsh[row][hcol] = __float2half(h0);
    }
    __syncthreads();

    const size_t OUT_HC = (size_t)LSEQ * NBATCH * HDIM;

#pragma unroll 1
    for (int t = 0; t < LSEQ; t++) {
        // --- prefetch Xg[t] and next-step masks (consumed after MMA) ---
        float xg[4][4];
        float mnext[4];
#pragma unroll
        for (int j = 0; j < 4; j++) {
            const int row = rb + 4 * j;
            const int n = n0 + row;
            const size_t base = ((size_t)t * NBATCH + n) * GDIM;
            xg[j][0] = g_Xg[base + hcol];
            xg[j][1] = g_Xg[base + hcol + 128];
            xg[j][2] = g_Xg[base + hcol + 256];
            xg[j][3] = g_Xg[base + hcol + 384];
            mnext[j] = (t < LSEQ - 1) ? (1.0f - (float)is_init[(size_t)(t + 1) * NBATCH + n])
                                      : 1.0f;
        }

        // --- MMA: gates_rec = h @ W_hh^T for this warp's 32 columns ---
        float acc[4][4];
#pragma unroll
        for (int j = 0; j < 4; j++)
#pragma unroll
            for (int q = 0; q < 4; q++) acc[j][q] = 0.0f;

#pragma unroll
        for (int kt = 0; kt < 8; kt++) {
            const int k = kt * 16 + (lane & 3) * 2;
            const int r = lane >> 2;
            uint32_t a0 = *reinterpret_cast<const uint32_t*>(&hsh[r][k]);
            uint32_t a1 = *reinterpret_cast<const uint32_t*>(&hsh[r + 8][k]);
            uint32_t a2 = *reinterpret_cast<const uint32_t*>(&hsh[r][k + 8]);
            uint32_t a3 = *reinterpret_cast<const uint32_t*>(&hsh[r + 8][k + 8]);
#pragma unroll
            for (int j = 0; j < 4; j++)
                mma16816(acc[j], a0, a1, a2, a3, bfrag[j][kt][0], bfrag[j][kt][1]);
        }

        // --- stage gate preacts to smem ---
#pragma unroll
        for (int j = 0; j < 4; j++) {
            const int col = colBase + j * 8 + (lane & 3) * 2;
            const int r = lane >> 2;
            *reinterpret_cast<float2*>(&gsh[r][col])     = make_float2(acc[j][0], acc[j][1]);
            *reinterpret_cast<float2*>(&gsh[r + 8][col]) = make_float2(acc[j][2], acc[j][3]);
        }
        __syncthreads();

        // --- epilogue: activations + state update (PyTorch gate order i,f,g,o) ---
#pragma unroll
        for (int j = 0; j < 4; j++) {
            const int row = rb + 4 * j;
            const int n = n0 + row;
            const float gi = gsh[row][hcol]       + xg[j][0];
            const float gf = gsh[row][hcol + 128] + xg[j][1];
            const float gg = gsh[row][hcol + 256] + xg[j][2];
            const float go = gsh[row][hcol + 384] + xg[j][3];

            const float i_ = sigf(gi);
            const float f_ = sigf(gf);
            const float g_ = tanh_fast(gg);
            const float o_ = sigf(go);

            const float cn = __fmaf_rn(f_, creg[j], i_ * g_);
            const float h  = o_ * tanh_fast(cn);

            out[((size_t)t * NBATCH + n) * HDIM + hcol] = h;

            // write-ahead masking for step t+1
            creg[j] = cn * mnext[j];
            hsh[row][hcol] = __float2half(h * mnext[j]);

            if (t == LSEQ - 1) {
                out[OUT_HC + (size_t)n * 256 + hcol]       = h;
                out[OUT_HC + (size_t)n * 256 + 128 + hcol] = cn;
            }
        }
        __syncthreads();
    }
}

// ---------------------------------------------------------------------------
extern "C" void kernel_launch(void* const* d_in, const int* in_sizes, int n_in,
                              void* d_out, int out_size)
{
    const float* input   = (const float*)d_in[0];  // [L,N,I] fp32
    const float* hc      = (const float*)d_in[1];  // [N,2H]  fp32
    const int*   is_init = (const int*)  d_in[2];  // [L,N]   int32
    const float* Wih     = (const float*)d_in[3];  // [4H,I]
    const float* Whh     = (const float*)d_in[4];  // [4H,H]
    const float* bih     = (const float*)d_in[5];  // [4H]
    const float* bhh     = (const float*)d_in[6];  // [4H]
    float* out = (float*)d_out;                    // [L,N,H] then [N,2H]

    pregemm_kernel<<<(LSEQ * NBATCH) / 32, 512>>>(input, Wih, bih, bhh);
    lstm_rec_kernel<<<NBATCH / 16, 512>>>(hc, is_init, Whh, out);
}

// round 2
// speedup vs baseline: 1.6425x; 1.6425x over previous
#include <cuda_runtime.h>
#include <cuda_fp16.h>
#include <cstdint>
#include <cstddef>

#define LSEQ 512
#define NBATCH 512
#define IDIM 128
#define HDIM 128
#define GDIM 512   // 4*H

// Scratch: packed fp16 pre-activation input gates.
// Layout: [m = t*N+n][colpair 0..63][gate 0..3][parity 0..1]  (16B per (m,cp))
__device__ __half g_XgH[(size_t)LSEQ * NBATCH * GDIM];

// ---------------------------------------------------------------------------
// helpers
// ---------------------------------------------------------------------------
__device__ __forceinline__ uint32_t f2h2(float a, float b) {
    __half2 h = __floats2half2_rn(a, b);
    return *reinterpret_cast<uint32_t*>(&h);
}

__device__ __forceinline__ void mma16816(float* d,
    uint32_t a0, uint32_t a1, uint32_t a2, uint32_t a3,
    uint32_t b0, uint32_t b1)
{
    asm volatile(
        "mma.sync.aligned.m16n8k16.row.col.f32.f16.f16.f32 "
        "{%0,%1,%2,%3}, {%4,%5,%6,%7}, {%8,%9}, {%0,%1,%2,%3};\n"
        : "+f"(d[0]), "+f"(d[1]), "+f"(d[2]), "+f"(d[3])
        : "r"(a0), "r"(a1), "r"(a2), "r"(a3), "r"(b0), "r"(b1));
}

__device__ __forceinline__ float ex2f(float x) {
    float y; asm("ex2.approx.f32 %0, %1;" : "=f"(y) : "f"(x)); return y;
}
__device__ __forceinline__ float rcpf(float x) {
    float y; asm("rcp.approx.f32 %0, %1;" : "=f"(y) : "f"(x)); return y;
}
// accurate sigmoid/tanh (EX2 ~2ulp, RCP ~1ulp) — NOT tanh.approx
__device__ __forceinline__ float sigf(float x) {
    return rcpf(1.0f + ex2f(-1.44269504f * x));
}
__device__ __forceinline__ float tanh_fast(float x) {
    return __fmaf_rn(2.0f, sigf(2.0f * x), -1.0f);
}

// ---------------------------------------------------------------------------
// Phase 1: Xg = x@W_ih^T + (b_ih+b_hh), stored packed fp16.
// Grid 2048 x 512 threads. 128 M-rows per block (4 subtiles of 32) so W_ih
// L2 traffic is 4x lower than 32-rows/block. Warp w owns gate cols [32w,32w+32).
// ---------------------------------------------------------------------------
__global__ void __launch_bounds__(512, 1)
pregemm_kernel(const float* __restrict__ x,
               const float* __restrict__ Wih,
               const float* __restrict__ bih,
               const float* __restrict__ bhh)
{
    __shared__ __half Ash[32][136];   // 272B pitch, conflict-free frags

    const int tid  = threadIdx.x;
    const int warp = tid >> 5;
    const int lane = tid & 31;
    const int q    = lane & 3;
    const int r0   = lane >> 2;
    const int colBase = warp * 32;

    // --- B fragments: W_ih rows for this warp's 32 gate columns (once) ---
    uint32_t bfrag[4][8][2];
#pragma unroll
    for (int j = 0; j < 4; j++) {
        const int nrow = colBase + j * 8 + r0;
        const float* wr = Wih + (size_t)nrow * IDIM;
#pragma unroll
        for (int kt = 0; kt < 8; kt++) {
            const int k = kt * 16 + q * 2;
            float2 w0 = *reinterpret_cast<const float2*>(wr + k);
            float2 w1 = *reinterpret_cast<const float2*>(wr + k + 8);
            bfrag[j][kt][0] = f2h2(w0.x, w0.y);
            bfrag[j][kt][1] = f2h2(w1.x, w1.y);
        }
    }

    // --- bias pairs for this lane's output columns ---
    float2 bsum[4];
#pragma unroll
    for (int j = 0; j < 4; j++) {
        const int col = colBase + j * 8 + q * 2;
        bsum[j].x = bih[col]     + bhh[col];
        bsum[j].y = bih[col + 1] + bhh[col + 1];
    }

#pragma unroll 1
    for (int s = 0; s < 4; s++) {
        const int m0 = blockIdx.x * 128 + s * 32;
        if (s) __syncthreads();             // protect Ash reuse

        // load + convert A tile (32 x 128 fp32 -> fp16 smem)
        {
            const int r = tid >> 4;
            const int c = (tid & 15) * 8;
            const float4* p = reinterpret_cast<const float4*>(x + (size_t)(m0 + r) * IDIM + c);
            float4 v0 = p[0];
            float4 v1 = p[1];
            __half2* sp = reinterpret_cast<__half2*>(&Ash[r][c]);
            sp[0] = __floats2half2_rn(v0.x, v0.y);
            sp[1] = __floats2half2_rn(v0.z, v0.w);
            sp[2] = __floats2half2_rn(v1.x, v1.y);
            sp[3] = __floats2half2_rn(v1.z, v1.w);
        }
        __syncthreads();

        float acc[2][4][4];
#pragma unroll
        for (int mi = 0; mi < 2; mi++)
#pragma unroll
            for (int j = 0; j < 4; j++)
#pragma unroll
                for (int p = 0; p < 4; p++) acc[mi][j][p] = 0.0f;

#pragma unroll
        for (int kt = 0; kt < 8; kt++) {
            const int k = kt * 16 + q * 2;
#pragma unroll
            for (int mi = 0; mi < 2; mi++) {
                const int r = mi * 16 + r0;
                uint32_t a0 = *reinterpret_cast<const uint32_t*>(&Ash[r][k]);
                uint32_t a1 = *reinterpret_cast<const uint32_t*>(&Ash[r + 8][k]);
                uint32_t a2 = *reinterpret_cast<const uint32_t*>(&Ash[r][k + 8]);
                uint32_t a3 = *reinterpret_cast<const uint32_t*>(&Ash[r + 8][k + 8]);
#pragma unroll
                for (int j = 0; j < 4; j++)
                    mma16816(acc[mi][j], a0, a1, a2, a3, bfrag[j][kt][0], bfrag[j][kt][1]);
            }
        }

        // epilogue: bias + fp16 packed store [row][cp][gate][parity]
#pragma unroll
        for (int mi = 0; mi < 2; mi++) {
#pragma unroll
            for (int j = 0; j < 4; j++) {
                const int row  = m0 + mi * 16 + r0;
                const int col  = colBase + j * 8 + q * 2;
                const int gate = col >> 7;
                const int hcp  = (col & 127) >> 1;
                __half2 v0 = __floats2half2_rn(acc[mi][j][0] + bsum[j].x,
                                               acc[mi][j][1] + bsum[j].y);
                __half2 v1 = __floats2half2_rn(acc[mi][j][2] + bsum[j].x,
                                               acc[mi][j][3] + bsum[j].y);
                *reinterpret_cast<__half2*>(&g_XgH[((size_t)row * 64 + hcp) * 8 + gate * 2])       = v0;
                *reinterpret_cast<__half2*>(&g_XgH[((size_t)(row + 8) * 64 + hcp) * 8 + gate * 2]) = v1;
            }
        }
    }
}

// ---------------------------------------------------------------------------
// Phase 2: masked LSTM recurrence.
// Grid 64 blocks x 8 batch rows, 512 threads (16 warps). Warp w owns hcols
// [8w,8w+8) for ALL FOUR gates (n8 tiles at col stride 128) -> the i/f/g/o
// pre-acts for each (row,hcol) land in the same lane: fully in-register
// epilogue, no gate-exchange smem, ONE barrier per step (double-buffered h).
// W_hh in per-warp B-fragments (loaded once). Xg prefetched one step ahead
// as a single LDG.128 per thread. Masks precomputed to smem.
// ---------------------------------------------------------------------------
__global__ void __launch_bounds__(512, 1)
lstm_rec_kernel(const float* __restrict__ hc,
                const int*   __restrict__ is_init,
                const float* __restrict__ Whh,
                float* __restrict__ out)
{
    __shared__ __half hbuf[2][16][136];   // double-buffered h (rows 8..15 zero)
    __shared__ float  msk[LSEQ][8];       // 16KB mask table

    const int tid  = threadIdx.x;
    const int warp = tid >> 5;
    const int lane = tid & 31;
    const int q    = lane & 3;
    const int r0   = lane >> 2;           // batch row 0..7
    const int n0   = blockIdx.x * 8;
    const int c0   = warp * 8 + q * 2;    // hcol pair base
    const int cp   = warp * 4 + q;        // colpair index 0..63
    const int n    = n0 + r0;

    // --- W_hh B-fragments: tile j covers cols j*128 + [8w, 8w+8) ---
    uint32_t bfrag[4][8][2];
#pragma unroll
    for (int j = 0; j < 4; j++) {
        const float* wr = Whh + (size_t)(j * 128 + warp * 8 + r0) * HDIM;
#pragma unroll
        for (int kt = 0; kt < 8; kt++) {
            const int k = kt * 16 + q * 2;
            float2 w0 = *reinterpret_cast<const float2*>(wr + k);
            float2 w1 = *reinterpret_cast<const float2*>(wr + k + 8);
            bfrag[j][kt][0] = f2h2(w0.x, w0.y);
            bfrag[j][kt][1] = f2h2(w1.x, w1.y);
        }
    }

    // --- precompute mask table; zero garbage rows 8..15 of both h buffers ---
    for (int idx = tid; idx < LSEQ * 8; idx += 512) {
        const int t = idx >> 3, r = idx & 7;
        msk[t][r] = 1.0f - (float)is_init[(size_t)t * NBATCH + n0 + r];
    }
    for (int idx = tid; idx < 2 * 8 * 136; idx += 512) {
        const int b = idx / (8 * 136), rem = idx % (8 * 136);
        hbuf[b][8 + rem / 136][rem % 136] = __half(0);
    }
    __syncthreads();

    // --- init state (t=0 mask applied) ---
    const float m0v = msk[0][r0];
    float creg0 = hc[(size_t)n * 256 + 128 + c0]     * m0v;
    float creg1 = hc[(size_t)n * 256 + 128 + c0 + 1] * m0v;
    {
        const float h00 = hc[(size_t)n * 256 + c0]     * m0v;
        const float h01 = hc[(size_t)n * 256 + c0 + 1] * m0v;
        *reinterpret_cast<__half2*>(&hbuf[0][r0][c0]) = __floats2half2_rn(h00, h01);
    }
    __syncthreads();

    const uint4* xgp = reinterpret_cast<const uint4*>(g_XgH);  // one uint4 per (m,cp)
    uint4 xcur = __ldg(&xgp[(size_t)n * 64 + cp]);             // t = 0

    const size_t OUT_HC = (size_t)LSEQ * NBATCH * HDIM;

#pragma unroll 1
    for (int t = 0; t < LSEQ; t++) {
        // prefetch next step's Xg (hidden behind MMA + epilogue + barrier)
        const int tn = (t < LSEQ - 1) ? t + 1 : t;
        uint4 xnext = __ldg(&xgp[((size_t)tn * NBATCH + n) * 64 + cp]);

        // --- MMA: all 4 gate tiles for this warp's 8 hcols ---
        const __half* hb = &hbuf[t & 1][0][0];
        float acc[4][4];
#pragma unroll
        for (int j = 0; j < 4; j++)
#pragma unroll
            for (int p = 0; p < 4; p++) acc[j][p] = 0.0f;

#pragma unroll
        for (int kt = 0; kt < 8; kt++) {
            const int k = kt * 16 + q * 2;
            uint32_t a0 = *reinterpret_cast<const uint32_t*>(hb + r0 * 136 + k);
            uint32_t a1 = *reinterpret_cast<const uint32_t*>(hb + (r0 + 8) * 136 + k);
            uint32_t a2 = *reinterpret_cast<const uint32_t*>(hb + r0 * 136 + k + 8);
            uint32_t a3 = *reinterpret_cast<const uint32_t*>(hb + (r0 + 8) * 136 + k + 8);
#pragma unroll
            for (int j = 0; j < 4; j++)
                mma16816(acc[j], a0, a1, a2, a3, bfrag[j][kt][0], bfrag[j][kt][1]);
        }

        // --- in-register epilogue (gate order i,f,g,o) ---
        const __half2* x2 = reinterpret_cast<const __half2*>(&xcur);
        const float2 xf0 = __half22float2(x2[0]);
        const float2 xf1 = __half22float2(x2[1]);
        const float2 xf2 = __half22float2(x2[2]);
        const float2 xf3 = __half22float2(x2[3]);

        const float mn = (t < LSEQ - 1) ? msk[t + 1][r0] : 1.0f;

        const float i0 = sigf(acc[0][0] + xf0.x);
        const float f0 = sigf(acc[1][0] + xf1.x);
        const float g0 = tanh_fast(acc[2][0] + xf2.x);
        const float o0 = sigf(acc[3][0] + xf3.x);
        const float cn0 = __fmaf_rn(f0, creg0, i0 * g0);
        const float hv0 = o0 * tanh_fast(cn0);

        const float i1 = sigf(acc[0][1] + xf0.y);
        const float f1 = sigf(acc[1][1] + xf1.y);
        const float g1 = tanh_fast(acc[2][1] + xf2.y);
        const float o1 = sigf(acc[3][1] + xf3.y);
        const float cn1 = __fmaf_rn(f1, creg1, i1 * g1);
        const float hv1 = o1 * tanh_fast(cn1);

        *reinterpret_cast<float2*>(&out[((size_t)t * NBATCH + n) * HDIM + c0]) =
            make_float2(hv0, hv1);

        creg0 = cn0 * mn;
        creg1 = cn1 * mn;
        *reinterpret_cast<__half2*>(&hbuf[(t + 1) & 1][r0][c0]) =
            __floats2half2_rn(hv0 * mn, hv1 * mn);

        if (t == LSEQ - 1) {
            *reinterpret_cast<float2*>(&out[OUT_HC + (size_t)n * 256 + c0]) =
                make_float2(hv0, hv1);
            *reinterpret_cast<float2*>(&out[OUT_HC + (size_t)n * 256 + 128 + c0]) =
                make_float2(cn0, cn1);
        }
        __syncthreads();
        xcur = xnext;
    }
}

// ---------------------------------------------------------------------------
extern "C" void kernel_launch(void* const* d_in, const int* in_sizes, int n_in,
                              void* d_out, int out_size)
{
    const float* input   = (const float*)d_in[0];  // [L,N,I] fp32
    const float* hc      = (const float*)d_in[1];  // [N,2H]  fp32
    const int*   is_init = (const int*)  d_in[2];  // [L,N]   int32
    const float* Wih     = (const float*)d_in[3];  // [4H,I]
    const float* Whh     = (const float*)d_in[4];  // [4H,H]
    const float* bih     = (const float*)d_in[5];  // [4H]
    const float* bhh     = (const float*)d_in[6];  // [4H]
    float* out = (float*)d_out;                    // [L,N,H] then [N,2H]

    pregemm_kernel<<<(LSEQ * NBATCH) / 128, 512>>>(input, Wih, bih, bhh);
    lstm_rec_kernel<<<NBATCH / 8, 512>>>(hc, is_init, Whh, out);
}

// round 3
// speedup vs baseline: 1.9254x; 1.1722x over previous
#include <cuda_runtime.h>
#include <cuda_fp16.h>
#include <cstdint>
#include <cstddef>

#define LSEQ 512
#define NBATCH 512
#define IDIM 128
#define HDIM 128
#define GDIM 512   // 4*H

// Scratch: packed fp16 pre-activation input gates.
// Layout: [m = t*N+n][hcol 0..127][gate 0..3]  -> 8 bytes per (m, hcol)
__device__ __half g_XgH[(size_t)LSEQ * NBATCH * GDIM];

// ---------------------------------------------------------------------------
// helpers
// ---------------------------------------------------------------------------
__device__ __forceinline__ uint32_t f2h2(float a, float b) {
    __half2 h = __floats2half2_rn(a, b);
    return *reinterpret_cast<uint32_t*>(&h);
}

__device__ __forceinline__ void mma16816(float* d,
    uint32_t a0, uint32_t a1, uint32_t a2, uint32_t a3,
    uint32_t b0, uint32_t b1)
{
    asm volatile(
        "mma.sync.aligned.m16n8k16.row.col.f32.f16.f16.f32 "
        "{%0,%1,%2,%3}, {%4,%5,%6,%7}, {%8,%9}, {%0,%1,%2,%3};\n"
        : "+f"(d[0]), "+f"(d[1]), "+f"(d[2]), "+f"(d[3])
        : "r"(a0), "r"(a1), "r"(a2), "r"(a3), "r"(b0), "r"(b1));
}

__device__ __forceinline__ void ldsm4(uint32_t& a0, uint32_t& a1,
                                      uint32_t& a2, uint32_t& a3, uint32_t saddr)
{
    asm volatile("ldmatrix.sync.aligned.m8n8.x4.shared.b16 {%0,%1,%2,%3}, [%4];"
                 : "=r"(a0), "=r"(a1), "=r"(a2), "=r"(a3) : "r"(saddr));
}

__device__ __forceinline__ float ex2f(float x) {
    float y; asm("ex2.approx.f32 %0, %1;" : "=f"(y) : "f"(x)); return y;
}
__device__ __forceinline__ float rcpf(float x) {
    float y; asm("rcp.approx.f32 %0, %1;" : "=f"(y) : "f"(x)); return y;
}
// accurate sigmoid/tanh (EX2 ~2ulp, RCP ~1ulp) — NOT tanh.approx
__device__ __forceinline__ float sigf(float x) {
    return rcpf(1.0f + ex2f(-1.44269504f * x));
}
__device__ __forceinline__ float tanh_fast(float x) {
    return __fmaf_rn(2.0f, sigf(2.0f * x), -1.0f);
}

// ---------------------------------------------------------------------------
// Phase 1: Xg = x@W_ih^T + (b_ih+b_hh), packed fp16 [m][hcol][gate].
// Grid 1024 x 512 threads. 256 M-rows/block, 8 subtiles of 32, double-buffered
// A smem with register prefetch: ONE barrier per subtile.
// Warp w owns hcols [8w, 8w+8) for ALL FOUR gates -> 16B coalesced stores.
// ---------------------------------------------------------------------------
__global__ void __launch_bounds__(512, 1)
pregemm_kernel(const float* __restrict__ x,
               const float* __restrict__ Wih,
               const float* __restrict__ bih,
               const float* __restrict__ bhh)
{
    __shared__ __half Ash[2][32][136];   // 272B pitch, conflict-free

    const int tid  = threadIdx.x;
    const int warp = tid >> 5;
    const int lane = tid & 31;
    const int q    = lane & 3;
    const int r0   = lane >> 2;
    const int c0   = warp * 8 + q * 2;   // hcol pair base (per-gate col)

    // --- B fragments: W_ih rows for gate tiles j at cols j*128 + [8w,8w+8) ---
    uint32_t bfrag[4][8][2];
#pragma unroll
    for (int j = 0; j < 4; j++) {
        const float* wr = Wih + (size_t)(j * 128 + warp * 8 + r0) * IDIM;
#pragma unroll
        for (int kt = 0; kt < 8; kt++) {
            const int k = kt * 16 + q * 2;
            float2 w0 = *reinterpret_cast<const float2*>(wr + k);
            float2 w1 = *reinterpret_cast<const float2*>(wr + k + 8);
            bfrag[j][kt][0] = f2h2(w0.x, w0.y);
            bfrag[j][kt][1] = f2h2(w1.x, w1.y);
        }
    }

    // --- bias per gate for cols c0, c0+1 ---
    float bx[4], by[4];
#pragma unroll
    for (int j = 0; j < 4; j++) {
        bx[j] = bih[j * 128 + c0]     + bhh[j * 128 + c0];
        by[j] = bih[j * 128 + c0 + 1] + bhh[j * 128 + c0 + 1];
    }

    // A-tile loader coords
    const int lr = tid >> 4;           // 0..31
    const int lc = (tid & 15) * 8;     // 0..120
    const size_t m_base = (size_t)blockIdx.x * 256;

    // ldmatrix lane address (within a buffer): row lane&15 (+16*mi), col (lane>>4)*8
    const int lm_row = lane & 15;
    const int lm_col = (lane >> 4) * 8;

    // prefetch subtile 0
    float4 v0 = *reinterpret_cast<const float4*>(x + (m_base + lr) * IDIM + lc);
    float4 v1 = *reinterpret_cast<const float4*>(x + (m_base + lr) * IDIM + lc + 4);

#pragma unroll 1
    for (int s = 0; s < 8; s++) {
        const int buf = s & 1;
        // store prefetched tile s
        {
            __half2* sp = reinterpret_cast<__half2*>(&Ash[buf][lr][lc]);
            sp[0] = __floats2half2_rn(v0.x, v0.y);
            sp[1] = __floats2half2_rn(v0.z, v0.w);
            sp[2] = __floats2half2_rn(v1.x, v1.y);
            sp[3] = __floats2half2_rn(v1.z, v1.w);
        }
        __syncthreads();

        // prefetch tile s+1 (hidden behind MMA)
        if (s < 7) {
            const size_t mr = m_base + (s + 1) * 32 + lr;
            v0 = *reinterpret_cast<const float4*>(x + mr * IDIM + lc);
            v1 = *reinterpret_cast<const float4*>(x + mr * IDIM + lc + 4);
        }

        float acc[2][4][4];
#pragma unroll
        for (int mi = 0; mi < 2; mi++)
#pragma unroll
            for (int j = 0; j < 4; j++)
#pragma unroll
                for (int p = 0; p < 4; p++) acc[mi][j][p] = 0.0f;

#pragma unroll
        for (int kt = 0; kt < 8; kt++) {
#pragma unroll
            for (int mi = 0; mi < 2; mi++) {
                uint32_t a0, a1, a2, a3;
                uint32_t saddr = (uint32_t)__cvta_generic_to_shared(
                    &Ash[buf][mi * 16 + lm_row][kt * 16 + lm_col]);
                ldsm4(a0, a1, a2, a3, saddr);
#pragma unroll
                for (int j = 0; j < 4; j++)
                    mma16816(acc[mi][j], a0, a1, a2, a3, bfrag[j][kt][0], bfrag[j][kt][1]);
            }
        }

        // epilogue: bias + packed fp16 store: 16B per (row, colpair)
        const size_t m0 = m_base + s * 32;
#pragma unroll
        for (int mi = 0; mi < 2; mi++) {
#pragma unroll
            for (int half_ = 0; half_ < 2; half_++) {
                const size_t row = m0 + mi * 16 + r0 + half_ * 8;
                const int pa = half_ * 2;      // regs [0,1] or [2,3]
                uint4 v;
                v.x = f2h2(acc[mi][0][pa]     + bx[0], acc[mi][1][pa]     + bx[1]);
                v.y = f2h2(acc[mi][2][pa]     + bx[2], acc[mi][3][pa]     + bx[3]);
                v.z = f2h2(acc[mi][0][pa + 1] + by[0], acc[mi][1][pa + 1] + by[1]);
                v.w = f2h2(acc[mi][2][pa + 1] + by[2], acc[mi][3][pa + 1] + by[3]);
                *reinterpret_cast<uint4*>(&g_XgH[(row * 128 + c0) * 4]) = v;
            }
        }
    }
}

// ---------------------------------------------------------------------------
// Phase 2: masked LSTM recurrence.
// Grid 128 blocks x 4 batch rows, 512 threads (16 warps). Warp w owns hcols
// [8w,8w+8) for all four gates. After MMA, gate pre-acts are shuffled so each
// lane owns exactly ONE (row, hcol) element -> MUFU per SMSP halved vs R2.
// ldmatrix.x4 for A-frags (8 LDSM/warp/step). One barrier per step.
// ---------------------------------------------------------------------------
__global__ void __launch_bounds__(512, 1)
lstm_rec_kernel(const float* __restrict__ hc,
                const int*   __restrict__ is_init,
                const float* __restrict__ Whh,
                float* __restrict__ out)
{
    __shared__ __half hbuf[2][16][136];   // double-buffered h (rows 4..15 zero)
    __shared__ float  msk[LSEQ][4];       // 8KB mask table

    const int tid  = threadIdx.x;
    const int warp = tid >> 5;
    const int lane = tid & 31;
    const int q    = lane & 3;
    const int r0   = lane >> 2;
    const int n0   = blockIdx.x * 4;

    // element ownership (post-shuffle): one element per lane
    const int er   = lane >> 3;                 // batch row 0..3
    const int ec   = lane & 7;                  // col idx in warp
    const int col  = warp * 8 + ec;             // global hcol
    const int n    = n0 + er;
    const int srcLane = er * 4 + (ec >> 1);     // lane holding this element's frags
    const int par  = ec & 1;

    // --- W_hh B-fragments: gate tile j covers cols j*128 + [8w,8w+8) ---
    uint32_t bfrag[4][8][2];
#pragma unroll
    for (int j = 0; j < 4; j++) {
        const float* wr = Whh + (size_t)(j * 128 + warp * 8 + r0) * HDIM;
#pragma unroll
        for (int kt = 0; kt < 8; kt++) {
            const int k = kt * 16 + q * 2;
            float2 w0 = *reinterpret_cast<const float2*>(wr + k);
            float2 w1 = *reinterpret_cast<const float2*>(wr + k + 8);
            bfrag[j][kt][0] = f2h2(w0.x, w0.y);
            bfrag[j][kt][1] = f2h2(w1.x, w1.y);
        }
    }

    // --- mask table + zero unused h rows of both buffers ---
    for (int idx = tid; idx < LSEQ * 4; idx += 512) {
        const int t = idx >> 2, r = idx & 3;
        msk[t][r] = 1.0f - (float)is_init[(size_t)t * NBATCH + n0 + r];
    }
    for (int idx = tid; idx < 2 * 12 * 136; idx += 512) {
        const int b = idx / (12 * 136), rem = idx % (12 * 136);
        hbuf[b][4 + rem / 136][rem % 136] = __half(0);
    }
    __syncthreads();

    // --- init state (t=0 mask applied); each lane owns one element ---
    const float m0v = msk[0][er];
    float creg = hc[(size_t)n * 256 + 128 + col] * m0v;
    hbuf[0][er][col] = __float2half(hc[(size_t)n * 256 + col] * m0v);
    __syncthreads();

    // per-lane Xg pointer: 8B per (m, hcol)
    const uint2* xgp = reinterpret_cast<const uint2*>(g_XgH);
    uint2 xcur = __ldg(&xgp[(size_t)n * 128 + col]);     // t = 0

    const int lm_row = lane & 15;
    const int lm_col = (lane >> 4) * 8;
    const size_t OUT_HC = (size_t)LSEQ * NBATCH * HDIM;

#pragma unroll 1
    for (int t = 0; t < LSEQ; t++) {
        // prefetch next step's Xg
        const int tn = (t < LSEQ - 1) ? t + 1 : t;
        uint2 xnext = __ldg(&xgp[((size_t)tn * NBATCH + n) * 128 + col]);

        // --- MMA: all 4 gate tiles for this warp's 8 hcols ---
        float acc[4][4];
#pragma unroll
        for (int j = 0; j < 4; j++)
#pragma unroll
            for (int p = 0; p < 4; p++) acc[j][p] = 0.0f;

        const uint32_t hb = (uint32_t)__cvta_generic_to_shared(
            &hbuf[t & 1][lm_row][lm_col]);
#pragma unroll
        for (int kt = 0; kt < 8; kt++) {
            uint32_t a0, a1, a2, a3;
            ldsm4(a0, a1, a2, a3, hb + kt * 32);
#pragma unroll
            for (int j = 0; j < 4; j++)
                mma16816(acc[j], a0, a1, a2, a3, bfrag[j][kt][0], bfrag[j][kt][1]);
        }

        // --- shuffle-redistribute: 1 element per lane ---
        float g[4];
#pragma unroll
        for (int j = 0; j < 4; j++) {
            const float v0 = __shfl_sync(0xffffffffu, acc[j][0], srcLane);
            const float v1 = __shfl_sync(0xffffffffu, acc[j][1], srcLane);
            g[j] = par ? v1 : v0;
        }

        // --- epilogue (gate order i,f,g,o) ---
        const float2 x01 = __half22float2(*reinterpret_cast<__half2*>(&xcur.x));
        const float2 x23 = __half22float2(*reinterpret_cast<__half2*>(&xcur.y));

        const float i_ = sigf(g[0] + x01.x);
        const float f_ = sigf(g[1] + x01.y);
        const float g_ = tanh_fast(g[2] + x23.x);
        const float o_ = sigf(g[3] + x23.y);
        const float cn = __fmaf_rn(f_, creg, i_ * g_);
        const float hv = o_ * tanh_fast(cn);

        out[((size_t)t * NBATCH + n) * HDIM + col] = hv;

        const float mn = (t < LSEQ - 1) ? msk[t + 1][er] : 1.0f;
        creg = cn * mn;
        hbuf[(t + 1) & 1][er][col] = __float2half(hv * mn);

        if (t == LSEQ - 1) {
            out[OUT_HC + (size_t)n * 256 + col]       = hv;
            out[OUT_HC + (size_t)n * 256 + 128 + col] = cn;
        }
        __syncthreads();
        xcur = xnext;
    }
}

// ---------------------------------------------------------------------------
extern "C" void kernel_launch(void* const* d_in, const int* in_sizes, int n_in,
                              void* d_out, int out_size)
{
    const float* input   = (const float*)d_in[0];  // [L,N,I] fp32
    const float* hc      = (const float*)d_in[1];  // [N,2H]  fp32
    const int*   is_init = (const int*)  d_in[2];  // [L,N]   int32
    const float* Wih     = (const float*)d_in[3];  // [4H,I]
    const float* Whh     = (const float*)d_in[4];  // [4H,H]
    const float* bih     = (const float*)d_in[5];  // [4H]
    const float* bhh     = (const float*)d_in[6];  // [4H]
    float* out = (float*)d_out;                    // [L,N,H] then [N,2H]

    pregemm_kernel<<<(LSEQ * NBATCH) / 256, 512>>>(input, Wih, bih, bhh);
    lstm_rec_kernel<<<NBATCH / 4, 512>>>(hc, is_init, Whh, out);
}